// round 1
// baseline (speedup 1.0000x reference)
#include <cuda_runtime.h>
#include <math.h>

// Problem constants (fixed shapes for BlurredMem_61950608278069)
#define BS 128
#define W  256
#define N  2048
#define R  4
#define EPSF 1e-8f

// Output layout (concatenation of reference tuple):
//   m_read  (BS,R,W)  at 0,            size 131072
//   M_new   (BS,W,N)  at OFF_MNEW,     size 67108864
//   read_wt (BS,R,N)  at OFF_RWT,      size 1048576
#define OFF_MNEW (BS*R*W)
#define OFF_RWT  (BS*R*W + BS*W*N)

// -------- scratch (device globals; no allocation allowed) --------
__device__ float  g_wkn[BS*W];       // normalized write key
__device__ float2 g_wmer[BS*W];      // (write_m, erase_vec)
__device__ float4 g_kn4[BS*W];       // normalized read keys, w-major, r packed in vec
__device__ float  g_wdist[BS*N];     // write dissimilarity logits
__device__ float  g_wwt[BS*N];       // write weights (softmax)
__device__ float  g_rdist[BS*R*N];   // read cosine logits

// -------- block reduction helpers (blockDim.x == 256) --------
__device__ __forceinline__ float blk_sum(float v, float* red) {
    int t = threadIdx.x;
    red[t] = v; __syncthreads();
    #pragma unroll
    for (int s = 128; s > 0; s >>= 1) {
        if (t < s) red[t] += red[t + s];
        __syncthreads();
    }
    float r = red[0]; __syncthreads();
    return r;
}
__device__ __forceinline__ float blk_max(float v, float* red) {
    int t = threadIdx.x;
    red[t] = v; __syncthreads();
    #pragma unroll
    for (int s = 128; s > 0; s >>= 1) {
        if (t < s) red[t] = fmaxf(red[t], red[t + s]);
        __syncthreads();
    }
    float r = red[0]; __syncthreads();
    return r;
}

// ===================== K1: per-batch prep =====================
// write_m, erase softmax, mix gate g, write_key (normalized), read keys (normalized)
__global__ void k1_prep(const float* __restrict__ k_r, const float* __restrict__ m_t,
                        const float* __restrict__ e_t, const float* __restrict__ m_er,
                        const float* __restrict__ gW,  const float* __restrict__ gb,
                        const float* __restrict__ oW,  const float* __restrict__ ob) {
    __shared__ float red[256];
    __shared__ float s_a[W], s_b[W];
    const int b = blockIdx.x, t = threadIdx.x;  // t == w == o

    float wm = tanhf(m_t[b*W + t]);
    float me = m_er[b*W + t];

    // erase = softmax(e_t) over W
    float e    = e_t[b*W + t];
    float emax = blk_max(e, red);
    float ex   = expf(e - emax);
    float esum = blk_sum(ex, red);
    float er   = ex / esum;

    // mix gate g = sigmoid([wm, me] . gW + gb)   (scalar per batch)
    float gs = blk_sum(wm * gW[t] + me * gW[W + t], red);
    float g  = 1.f / (1.f + expf(-(gs + gb[0])));

    s_a[t] = g * wm;
    s_b[t] = (1.f - g) * me;
    __syncthreads();

    // write_key[o] = relu( sum_w a[w]*oW[o,w] + b[w]*oW[o,W+w] + ob[o] )
    const float* orow = oW + t * (2 * W);
    float acc = ob[t];
    #pragma unroll 4
    for (int w = 0; w < W; w++)
        acc += s_a[w] * orow[w] + s_b[w] * orow[W + w];
    float wk = fmaxf(acc, 0.f);

    float wn2 = blk_sum(wk * wk, red);
    g_wkn[b*W + t]  = wk / (sqrtf(wn2) + EPSF);
    g_wmer[b*W + t] = make_float2(wm, er);

    // normalized read keys
    float kv[R];
    #pragma unroll
    for (int r = 0; r < R; r++) kv[r] = tanhf(k_r[(b*R + r) * W + t]);
    #pragma unroll
    for (int r = 0; r < R; r++) {
        float n2 = blk_sum(kv[r] * kv[r], red);
        kv[r] /= (sqrtf(n2) + EPSF);
    }
    g_kn4[b*W + t] = make_float4(kv[0], kv[1], kv[2], kv[3]);
}

// ===================== K2: write dissimilarity =====================
// one thread per column n; coalesced streaming of memory (256 MB)
__global__ void k2_wdist(const float* __restrict__ mem) {
    __shared__ float s_wkn[W];
    const int b = blockIdx.y;
    const int n = blockIdx.x * 256 + threadIdx.x;
    s_wkn[threadIdx.x] = g_wkn[b*W + threadIdx.x];
    __syncthreads();

    const float* mp = mem + (size_t)b * W * N + n;
    float sq = 0.f, dot = 0.f;
    #pragma unroll 8
    for (int w = 0; w < W; w++) {
        float v = mp[(size_t)w * N];
        sq  += v * v;
        dot += v * s_wkn[w];
    }
    g_wdist[b*N + n] = -dot / (sqrtf(sq) + EPSF);
}

// ===================== softmax over N (rows of length N) =====================
__global__ void k_softmax(const float* __restrict__ in, float* __restrict__ out) {
    __shared__ float red[256];
    const int row = blockIdx.x, t = threadIdx.x;
    const float* ip = in + (size_t)row * N;

    float v[8]; float m = -1e30f;
    #pragma unroll
    for (int i = 0; i < 8; i++) { v[i] = ip[t + i*256]; m = fmaxf(m, v[i]); }
    m = blk_max(m, red);
    float s = 0.f;
    #pragma unroll
    for (int i = 0; i < 8; i++) { v[i] = expf(v[i] - m); s += v[i]; }
    s = blk_sum(s, red);
    float inv = 1.f / s;
    float* op = out + (size_t)row * N;
    #pragma unroll
    for (int i = 0; i < 8; i++) op[t + i*256] = v[i] * inv;
}

// ===================== K4: M_new + read logits =====================
// one thread per column n; reads memory, writes M_new, accumulates column
// norm and R read-key dots in registers. 512 MB of HBM traffic.
__global__ void k4_update(const float* __restrict__ mem, float* __restrict__ Mnew) {
    __shared__ float2 s_wmer[W];
    __shared__ float4 s_kn[W];
    const int b = blockIdx.y;
    const int n = blockIdx.x * 256 + threadIdx.x;
    const int t = threadIdx.x;
    s_wmer[t] = g_wmer[b*W + t];
    s_kn[t]   = g_kn4[b*W + t];
    __syncthreads();

    const float wwt = g_wwt[b*N + n];
    const float* mp = mem  + (size_t)b * W * N + n;
    float*       op = Mnew + (size_t)b * W * N + n;

    float sq = 0.f, d0 = 0.f, d1 = 0.f, d2 = 0.f, d3 = 0.f;
    #pragma unroll 4
    for (int w = 0; w < W; w++) {
        float v   = mp[(size_t)w * N];
        float2 we = s_wmer[w];
        float mn  = v * (1.f - we.y * wwt) + we.x * wwt;
        op[(size_t)w * N] = mn;
        sq += mn * mn;
        float4 k = s_kn[w];
        d0 += mn * k.x; d1 += mn * k.y; d2 += mn * k.z; d3 += mn * k.w;
    }
    float inv = 1.f / (sqrtf(sq) + EPSF);
    g_rdist[((size_t)b*R + 0)*N + n] = d0 * inv;
    g_rdist[((size_t)b*R + 1)*N + n] = d1 * inv;
    g_rdist[((size_t)b*R + 2)*N + n] = d2 * inv;
    g_rdist[((size_t)b*R + 3)*N + n] = d3 * inv;
}

// ===================== K6: m_read = read_wt . M_new^T =====================
// grid (W, BS): block (w,b) reduces over n with float4 loads (256 MB read)
__global__ void k6_mread(const float* __restrict__ Mnew, const float* __restrict__ rwt,
                         float* __restrict__ mread) {
    __shared__ float red[256];
    const int b = blockIdx.y, w = blockIdx.x, t = threadIdx.x;
    const float4* mp = (const float4*)(Mnew + ((size_t)b * W + w) * N);
    const float4* r0 = (const float4*)(rwt + ((size_t)b*R + 0) * N);
    const float4* r1 = (const float4*)(rwt + ((size_t)b*R + 1) * N);
    const float4* r2 = (const float4*)(rwt + ((size_t)b*R + 2) * N);
    const float4* r3 = (const float4*)(rwt + ((size_t)b*R + 3) * N);

    float a0 = 0.f, a1 = 0.f, a2 = 0.f, a3 = 0.f;
    #pragma unroll
    for (int i = 0; i < (N/4)/256; i++) {   // 2 iterations
        int idx = t + i * 256;
        float4 v  = mp[idx];
        float4 q0 = r0[idx];
        float4 q1 = r1[idx];
        float4 q2 = r2[idx];
        float4 q3 = r3[idx];
        a0 += v.x*q0.x + v.y*q0.y + v.z*q0.z + v.w*q0.w;
        a1 += v.x*q1.x + v.y*q1.y + v.z*q1.z + v.w*q1.w;
        a2 += v.x*q2.x + v.y*q2.y + v.z*q2.z + v.w*q2.w;
        a3 += v.x*q3.x + v.y*q3.y + v.z*q3.z + v.w*q3.w;
    }
    a0 = blk_sum(a0, red);
    a1 = blk_sum(a1, red);
    a2 = blk_sum(a2, red);
    a3 = blk_sum(a3, red);
    if (t == 0) {
        float* o = mread + (size_t)b * R * W + w;
        o[0]     = a0;
        o[W]     = a1;
        o[2*W]   = a2;
        o[3*W]   = a3;
    }
}

// ===================== launch =====================
extern "C" void kernel_launch(void* const* d_in, const int* in_sizes, int n_in,
                              void* d_out, int out_size) {
    const float* k_r   = (const float*)d_in[0];
    const float* m_t   = (const float*)d_in[1];
    const float* e_t   = (const float*)d_in[2];
    const float* m_er  = (const float*)d_in[3];
    const float* mem   = (const float*)d_in[4];
    const float* gW    = (const float*)d_in[5];
    const float* gb    = (const float*)d_in[6];
    const float* oW    = (const float*)d_in[7];
    const float* ob    = (const float*)d_in[8];

    float* out    = (float*)d_out;
    float* mread  = out;              // (BS,R,W)
    float* Mnew   = out + OFF_MNEW;   // (BS,W,N)
    float* rwt    = out + OFF_RWT;    // (BS,R,N)

    float* d_wdist; cudaGetSymbolAddress((void**)&d_wdist, g_wdist);
    float* d_wwt;   cudaGetSymbolAddress((void**)&d_wwt,   g_wwt);
    float* d_rdist; cudaGetSymbolAddress((void**)&d_rdist, g_rdist);

    k1_prep<<<BS, 256>>>(k_r, m_t, e_t, m_er, gW, gb, oW, ob);
    k2_wdist<<<dim3(N/256, BS), 256>>>(mem);
    k_softmax<<<BS, 256>>>(d_wdist, d_wwt);
    k4_update<<<dim3(N/256, BS), 256>>>(mem, Mnew);
    k_softmax<<<BS*R, 256>>>(d_rdist, rwt);
    k6_mread<<<dim3(W, BS), 256>>>(Mnew, rwt, mread);
}

// round 2
// speedup vs baseline: 1.2945x; 1.2945x over previous
#include <cuda_runtime.h>
#include <math.h>

// Problem constants (fixed shapes for BlurredMem_61950608278069)
#define BS 128
#define W  256
#define N  2048
#define R  4
#define EPSF 1e-8f
#define CH 8                      // n-chunks for k2/k4 (N / 256)

// Output layout: m_read (BS,R,W) | M_new (BS,W,N) | read_wt (BS,R,N)
#define OFF_MNEW (BS*R*W)
#define OFF_RWT  (BS*R*W + BS*W*N)

// -------- scratch (device globals; no allocation allowed) --------
__device__ float  g_wkn[BS*W];        // normalized write key
__device__ float2 g_wmer[BS*W];       // (write_m, erase_vec)
__device__ float4 g_kn4[BS*W];        // normalized read keys (r packed)
__device__ float  g_we[BS*N];         // exp(-cos) unnormalized write weights
__device__ float  g_Zw_part[BS*CH];   // per-block partial sums of g_we
__device__ float  g_rexp[BS*R*N];     // exp(cos) unnormalized read weights
__device__ float  g_Zr_part[BS*CH*R]; // per-block partial sums per read head

// -------- block reduction: warp shuffles + one smem pass (256 threads) ----
template<int NV>
__device__ __forceinline__ void blk_reduce_sum(float (&v)[NV], float* sbuf) {
    const int lane = threadIdx.x & 31, wid = threadIdx.x >> 5;
    #pragma unroll
    for (int i = 0; i < NV; i++) {
        float x = v[i];
        #pragma unroll
        for (int o = 16; o; o >>= 1) x += __shfl_xor_sync(0xffffffffu, x, o);
        if (lane == 0) sbuf[i*8 + wid] = x;
    }
    __syncthreads();
    #pragma unroll
    for (int i = 0; i < NV; i++) {
        float s = 0.f;
        #pragma unroll
        for (int j = 0; j < 8; j++) s += sbuf[i*8 + j];
        v[i] = s;
    }
    __syncthreads();
}

// ===================== K1: per-batch prep =====================
__global__ void k1_prep(const float* __restrict__ k_r, const float* __restrict__ m_t,
                        const float* __restrict__ e_t, const float* __restrict__ m_er,
                        const float* __restrict__ gW,  const float* __restrict__ gb,
                        const float* __restrict__ oW,  const float* __restrict__ ob) {
    __shared__ float sbuf[48];
    __shared__ __align__(16) float s_a[W], s_b[W];
    const int b = blockIdx.x, t = threadIdx.x;      // t == w == o

    const float wm = tanhf(m_t[b*W + t]);
    const float me = m_er[b*W + t];
    const float ex = expf(e_t[b*W + t]);            // erase softmax (no max pass)

    float kv[R];
    #pragma unroll
    for (int r = 0; r < R; r++) kv[r] = tanhf(k_r[(b*R + r)*W + t]);

    // fused reduction: {esum, gate logit, 4 read-key norms}
    float v[6];
    v[0] = ex;
    v[1] = wm * gW[t] + me * gW[W + t];
    #pragma unroll
    for (int r = 0; r < R; r++) v[2+r] = kv[r] * kv[r];
    blk_reduce_sum<6>(v, sbuf);

    const float er = ex / v[0];
    const float g  = 1.f / (1.f + expf(-(v[1] + gb[0])));

    s_a[t] = g * wm;
    s_b[t] = (1.f - g) * me;
    __syncthreads();

    // write_key[o] = relu( a . oW[o,0:W] + b . oW[o,W:2W] + ob[o] ), float4
    const float4* orow4 = (const float4*)(oW + (size_t)t * 2 * W);
    const float4* sa4   = (const float4*)s_a;
    const float4* sb4   = (const float4*)s_b;
    float acc = ob[t];
    #pragma unroll 8
    for (int j = 0; j < W/4; j++) {
        float4 oa = orow4[j],        sa = sa4[j];
        float4 obv = orow4[W/4 + j], sb = sb4[j];
        acc += oa.x*sa.x + oa.y*sa.y + oa.z*sa.z + oa.w*sa.w;
        acc += obv.x*sb.x + obv.y*sb.y + obv.z*sb.z + obv.w*sb.w;
    }
    const float wk = fmaxf(acc, 0.f);

    float v2[1] = { wk * wk };
    blk_reduce_sum<1>(v2, sbuf);

    g_wkn[b*W + t]  = wk / (sqrtf(v2[0]) + EPSF);
    g_wmer[b*W + t] = make_float2(wm, er);
    #pragma unroll
    for (int r = 0; r < R; r++) kv[r] /= (sqrtf(v[2+r]) + EPSF);
    g_kn4[b*W + t] = make_float4(kv[0], kv[1], kv[2], kv[3]);
}

// ===================== K2: unnormalized write weights =====================
__global__ void k2_wdist(const float* __restrict__ mem) {
    __shared__ float s_wkn[W];
    __shared__ float sbuf[8];
    const int b = blockIdx.y;
    const int n = blockIdx.x * 256 + threadIdx.x;
    s_wkn[threadIdx.x] = g_wkn[b*W + threadIdx.x];
    __syncthreads();

    const float* mp = mem + (size_t)b * W * N + n;
    float sq = 0.f, dot = 0.f;
    #pragma unroll 8
    for (int w = 0; w < W; w++) {
        float v = mp[(size_t)w * N];
        sq  += v * v;
        dot += v * s_wkn[w];
    }
    const float e = expf(-dot / (sqrtf(sq) + EPSF));   // exp(-cos) in [e^-1, e]
    g_we[b*N + n] = e;

    float v1[1] = { e };
    blk_reduce_sum<1>(v1, sbuf);
    if (threadIdx.x == 0) g_Zw_part[b*CH + blockIdx.x] = v1[0];
}

// ===================== K4: M_new + unnormalized read weights ==============
__global__ void k4_update(const float* __restrict__ mem, float* __restrict__ Mnew) {
    __shared__ float2 s_wmer[W];
    __shared__ float4 s_kn[W];
    __shared__ float  sbuf[32];
    const int b = blockIdx.y, t = threadIdx.x;
    const int n = blockIdx.x * 256 + t;
    s_wmer[t] = g_wmer[b*W + t];
    s_kn[t]   = g_kn4[b*W + t];

    float zw = 0.f;
    #pragma unroll
    for (int c = 0; c < CH; c++) zw += g_Zw_part[b*CH + c];
    __syncthreads();

    const float wwt = g_we[b*N + n] / zw;
    const float* mp = mem  + (size_t)b * W * N + n;
    float*       op = Mnew + (size_t)b * W * N + n;

    float sq = 0.f, d0 = 0.f, d1 = 0.f, d2 = 0.f, d3 = 0.f;
    #pragma unroll 8
    for (int w = 0; w < W; w++) {
        float  v  = mp[(size_t)w * N];
        float2 we = s_wmer[w];
        float  mn = v * (1.f - we.y * wwt) + we.x * wwt;
        op[(size_t)w * N] = mn;
        sq += mn * mn;
        float4 k = s_kn[w];
        d0 += mn * k.x; d1 += mn * k.y; d2 += mn * k.z; d3 += mn * k.w;
    }
    const float inv = 1.f / (sqrtf(sq) + EPSF);
    float e[R];
    e[0] = expf(d0 * inv); e[1] = expf(d1 * inv);
    e[2] = expf(d2 * inv); e[3] = expf(d3 * inv);
    #pragma unroll
    for (int r = 0; r < R; r++) g_rexp[((size_t)b*R + r)*N + n] = e[r];

    blk_reduce_sum<R>(e, sbuf);
    if (t == 0) {
        #pragma unroll
        for (int r = 0; r < R; r++) g_Zr_part[(b*CH + blockIdx.x)*R + r] = e[r];
    }
}

// ===================== K6: rwt output + m_read ============================
// block = (wgroup of 8 rows, b). Stages normalized read weights in smem once,
// then each warp streams one contiguous M_new row (float4, coalesced) against
// conflict-free LDS.128 of s_e, with a warp-shuffle reduction. No barriers in
// the hot loop, no redundant rwt traffic.
__global__ void k6_read(const float* __restrict__ Mnew, float* __restrict__ rwt,
                        float* __restrict__ mread) {
    __shared__ float s_e[R][N];     // 32 KB
    const int b = blockIdx.y, wg = blockIdx.x;
    const int t = threadIdx.x, lane = t & 31, wi = t >> 5;

    float invZ[R];
    #pragma unroll
    for (int r = 0; r < R; r++) {
        float z = 0.f;
        #pragma unroll
        for (int c = 0; c < CH; c++) z += g_Zr_part[(b*CH + c)*R + r];
        invZ[r] = 1.f / z;
    }

    const bool write_rwt = (wg == 0);
    #pragma unroll
    for (int k = 0; k < N/256; k++) {
        const int n = t + k * 256;
        #pragma unroll
        for (int r = 0; r < R; r++) {
            float val = g_rexp[((size_t)b*R + r)*N + n] * invZ[r];
            s_e[r][n] = val;
            if (write_rwt) rwt[((size_t)b*R + r)*N + n] = val;
        }
    }
    __syncthreads();

    const int w = wg * 8 + wi;
    const float4* row4 = (const float4*)(Mnew + ((size_t)b * W + w) * N);
    float a0 = 0.f, a1 = 0.f, a2 = 0.f, a3 = 0.f;
    #pragma unroll 4
    for (int k = 0; k < (N/4)/32; k++) {        // 16 iterations
        const int idx = lane + k * 32;
        float4 v  = row4[idx];
        float4 e0 = *(const float4*)&s_e[0][idx*4];
        float4 e1 = *(const float4*)&s_e[1][idx*4];
        float4 e2 = *(const float4*)&s_e[2][idx*4];
        float4 e3 = *(const float4*)&s_e[3][idx*4];
        a0 += v.x*e0.x + v.y*e0.y + v.z*e0.z + v.w*e0.w;
        a1 += v.x*e1.x + v.y*e1.y + v.z*e1.z + v.w*e1.w;
        a2 += v.x*e2.x + v.y*e2.y + v.z*e2.z + v.w*e2.w;
        a3 += v.x*e3.x + v.y*e3.y + v.z*e3.z + v.w*e3.w;
    }
    #pragma unroll
    for (int o = 16; o; o >>= 1) {
        a0 += __shfl_xor_sync(0xffffffffu, a0, o);
        a1 += __shfl_xor_sync(0xffffffffu, a1, o);
        a2 += __shfl_xor_sync(0xffffffffu, a2, o);
        a3 += __shfl_xor_sync(0xffffffffu, a3, o);
    }
    if (lane == 0) {
        float* o = mread + (size_t)b * R * W + w;
        o[0]     = a0;
        o[W]     = a1;
        o[2*W]   = a2;
        o[3*W]   = a3;
    }
}

// ===================== launch =====================
extern "C" void kernel_launch(void* const* d_in, const int* in_sizes, int n_in,
                              void* d_out, int out_size) {
    const float* k_r   = (const float*)d_in[0];
    const float* m_t   = (const float*)d_in[1];
    const float* e_t   = (const float*)d_in[2];
    const float* m_er  = (const float*)d_in[3];
    const float* mem   = (const float*)d_in[4];
    const float* gW    = (const float*)d_in[5];
    const float* gb    = (const float*)d_in[6];
    const float* oW    = (const float*)d_in[7];
    const float* ob    = (const float*)d_in[8];

    float* out   = (float*)d_out;
    float* mread = out;               // (BS,R,W)
    float* Mnew  = out + OFF_MNEW;    // (BS,W,N)
    float* rwt   = out + OFF_RWT;     // (BS,R,N)

    k1_prep <<<BS, 256>>>(k_r, m_t, e_t, m_er, gW, gb, oW, ob);
    k2_wdist<<<dim3(CH, BS), 256>>>(mem);
    k4_update<<<dim3(CH, BS), 256>>>(mem, Mnew);
    k6_read <<<dim3(W/8, BS), 256>>>(Mnew, rwt, mread);
}

// round 3
// speedup vs baseline: 1.7517x; 1.3532x over previous
#include <cuda_runtime.h>
#include <math.h>

// Fixed shapes for BlurredMem_61950608278069
#define BS 128
#define W  256
#define N  2048
#define R  4
#define EPSF 1e-8f
#define CH 4                       // n-chunks for k2/k4 (512 n per block)

// Output layout: m_read (BS,R,W) | M_new (BS,W,N) | read_wt (BS,R,N)
#define OFF_MNEW (BS*R*W)
#define OFF_RWT  (BS*R*W + BS*W*N)

// -------- scratch (device globals) --------
__device__ float  g_wk[BS*W];         // UNNORMALIZED write key (relu'd)
__device__ float2 g_wmer[BS*W];       // (write_m, erase_vec)
__device__ float4 g_kn4[BS*W];        // normalized read keys (r packed)
__device__ float  g_we[BS*N];         // exp(-cos) unnormalized write weights
__device__ float  g_Zw_part[BS*CH];   // per-block partial sums of g_we
__device__ float  g_rexp[BS*R*N];     // exp(cos) unnormalized read weights
__device__ float  g_Zr_part[BS*CH*R]; // per-block partial sums per read head

// -------- block reduction: warp shuffles + one smem pass (256 threads) ----
template<int NV>
__device__ __forceinline__ void blk_reduce_sum(float (&v)[NV], float* sbuf) {
    const int lane = threadIdx.x & 31, wid = threadIdx.x >> 5;
    #pragma unroll
    for (int i = 0; i < NV; i++) {
        float x = v[i];
        #pragma unroll
        for (int o = 16; o; o >>= 1) x += __shfl_xor_sync(0xffffffffu, x, o);
        if (lane == 0) sbuf[i*8 + wid] = x;
    }
    __syncthreads();
    #pragma unroll
    for (int i = 0; i < NV; i++) {
        float s = 0.f;
        #pragma unroll
        for (int j = 0; j < 8; j++) s += sbuf[i*8 + j];
        v[i] = s;
    }
    __syncthreads();
}

// ===================== K1: per-batch prep (grid 4 x BS) =====================
// All 4 blocks per batch redundantly do the cheap W-wide reductions; each
// block then computes 64 MLP output rows with 4 threads per row.
__global__ void k1_prep(const float* __restrict__ k_r, const float* __restrict__ m_t,
                        const float* __restrict__ e_t, const float* __restrict__ m_er,
                        const float* __restrict__ gW,  const float* __restrict__ gb,
                        const float* __restrict__ oW,  const float* __restrict__ ob) {
    __shared__ float sbuf[48];
    __shared__ __align__(16) float s_cat[2*W];
    const int b = blockIdx.y, t = threadIdx.x;      // t == w in phase 1

    const float wm = tanhf(m_t[b*W + t]);
    const float me = m_er[b*W + t];
    const float ex = expf(e_t[b*W + t]);            // erase softmax, no max pass

    float kv[R];
    #pragma unroll
    for (int r = 0; r < R; r++) kv[r] = tanhf(k_r[(b*R + r)*W + t]);

    float v[6];
    v[0] = ex;
    v[1] = wm * gW[t] + me * gW[W + t];
    #pragma unroll
    for (int r = 0; r < R; r++) v[2+r] = kv[r] * kv[r];
    blk_reduce_sum<6>(v, sbuf);

    const float g = 1.f / (1.f + expf(-(v[1] + gb[0])));
    s_cat[t]     = g * wm;
    s_cat[W + t] = (1.f - g) * me;

    if (blockIdx.x == 0) {
        g_wmer[b*W + t] = make_float2(wm, ex / v[0]);
        #pragma unroll
        for (int r = 0; r < R; r++) kv[r] /= (sqrtf(v[2+r]) + EPSF);
        g_kn4[b*W + t] = make_float4(kv[0], kv[1], kv[2], kv[3]);
    }
    __syncthreads();

    // MLP: 64 rows per block, 4 threads per row (part p handles j = 4i+p)
    const int o = blockIdx.x * 64 + (t >> 2);
    const int p = t & 3;
    const float4* orow4 = (const float4*)(oW + (size_t)o * 2 * W);
    const float4* sc4   = (const float4*)s_cat;
    float acc = 0.f;
    #pragma unroll 8
    for (int i = 0; i < 32; i++) {
        const int j = 4*i + p;
        float4 ow = orow4[j], sc = sc4[j];
        acc += ow.x*sc.x + ow.y*sc.y + ow.z*sc.z + ow.w*sc.w;
    }
    acc += __shfl_xor_sync(0xffffffffu, acc, 1);
    acc += __shfl_xor_sync(0xffffffffu, acc, 2);
    if (p == 0) g_wk[b*W + o] = fmaxf(acc + ob[o], 0.f);
}

// ===================== K2: unnormalized write weights =====================
// thread owns 2 columns (float2); also normalizes the write key in-block
__global__ void k2_wdist(const float* __restrict__ mem) {
    __shared__ float s_wkn[W];
    __shared__ float sbuf[8];
    const int b = blockIdx.y, t = threadIdx.x;
    const int n0 = blockIdx.x * 512 + 2 * t;

    const float wk = g_wk[b*W + t];
    float v1[1] = { wk * wk };
    blk_reduce_sum<1>(v1, sbuf);
    s_wkn[t] = wk / (sqrtf(v1[0]) + EPSF);
    __syncthreads();

    const float2* mp = (const float2*)(mem + (size_t)b * W * N + n0);
    float2 sq = make_float2(0.f, 0.f), dot = make_float2(0.f, 0.f);
    #pragma unroll 8
    for (int w = 0; w < W; w++) {
        float2 mv = mp[(size_t)w * (N/2)];
        float  kn = s_wkn[w];
        sq.x  += mv.x * mv.x;  sq.y  += mv.y * mv.y;
        dot.x += mv.x * kn;    dot.y += mv.y * kn;
    }
    float2 e;
    e.x = expf(-dot.x / (sqrtf(sq.x) + EPSF));
    e.y = expf(-dot.y / (sqrtf(sq.y) + EPSF));
    *(float2*)&g_we[b*N + n0] = e;

    float z[1] = { e.x + e.y };
    blk_reduce_sum<1>(z, sbuf);
    if (t == 0) g_Zw_part[b*CH + blockIdx.x] = z[0];
}

// ===================== K4: M_new + unnormalized read weights ==============
__global__ void k4_update(const float* __restrict__ mem, float* __restrict__ Mnew) {
    __shared__ float2 s_wmer[W];
    __shared__ float4 s_kn[W];
    __shared__ float  sbuf[32];
    const int b = blockIdx.y, t = threadIdx.x;
    const int n0 = blockIdx.x * 512 + 2 * t;
    s_wmer[t] = g_wmer[b*W + t];
    s_kn[t]   = g_kn4[b*W + t];

    float zw = 0.f;
    #pragma unroll
    for (int c = 0; c < CH; c++) zw += g_Zw_part[b*CH + c];
    __syncthreads();

    float2 wev = *(const float2*)&g_we[b*N + n0];
    const float2 wwt = make_float2(wev.x / zw, wev.y / zw);
    const float2* mp = (const float2*)(mem  + (size_t)b * W * N + n0);
    float2*       op = (float2*)(Mnew + (size_t)b * W * N + n0);

    float2 sq = make_float2(0.f, 0.f);
    float2 d0 = sq, d1 = sq, d2 = sq, d3 = sq;
    #pragma unroll 8
    for (int w = 0; w < W; w++) {
        float2 mv = mp[(size_t)w * (N/2)];
        float2 we = s_wmer[w];
        float2 mn;
        mn.x = mv.x * (1.f - we.y * wwt.x) + we.x * wwt.x;
        mn.y = mv.y * (1.f - we.y * wwt.y) + we.x * wwt.y;
        op[(size_t)w * (N/2)] = mn;
        sq.x += mn.x * mn.x;  sq.y += mn.y * mn.y;
        float4 k = s_kn[w];
        d0.x += mn.x * k.x;  d0.y += mn.y * k.x;
        d1.x += mn.x * k.y;  d1.y += mn.y * k.y;
        d2.x += mn.x * k.z;  d2.y += mn.y * k.z;
        d3.x += mn.x * k.w;  d3.y += mn.y * k.w;
    }
    const float ivx = 1.f / (sqrtf(sq.x) + EPSF);
    const float ivy = 1.f / (sqrtf(sq.y) + EPSF);
    float2 e0 = make_float2(expf(d0.x*ivx), expf(d0.y*ivy));
    float2 e1 = make_float2(expf(d1.x*ivx), expf(d1.y*ivy));
    float2 e2 = make_float2(expf(d2.x*ivx), expf(d2.y*ivy));
    float2 e3 = make_float2(expf(d3.x*ivx), expf(d3.y*ivy));
    *(float2*)&g_rexp[((size_t)b*R + 0)*N + n0] = e0;
    *(float2*)&g_rexp[((size_t)b*R + 1)*N + n0] = e1;
    *(float2*)&g_rexp[((size_t)b*R + 2)*N + n0] = e2;
    *(float2*)&g_rexp[((size_t)b*R + 3)*N + n0] = e3;

    float zr[R] = { e0.x+e0.y, e1.x+e1.y, e2.x+e2.y, e3.x+e3.y };
    blk_reduce_sum<R>(zr, sbuf);
    if (t == 0) {
        #pragma unroll
        for (int r = 0; r < R; r++) g_Zr_part[(b*CH + blockIdx.x)*R + r] = zr[r];
    }
}

// ===================== K6: rwt output + m_read ============================
// block = (group of 32 rows, b); each warp owns 4 consecutive M_new rows so
// the 4 e-row LDS.128 are amortized over 4 LDG.128 streams.
__global__ void k6_read(const float* __restrict__ Mnew, float* __restrict__ rwt,
                        float* __restrict__ mread) {
    __shared__ __align__(16) float s_e[R][N];     // 32 KB
    const int b = blockIdx.y, wg = blockIdx.x;
    const int t = threadIdx.x, lane = t & 31, wi = t >> 5;

    float invZ[R];
    #pragma unroll
    for (int r = 0; r < R; r++) {
        float z = 0.f;
        #pragma unroll
        for (int c = 0; c < CH; c++) z += g_Zr_part[(b*CH + c)*R + r];
        invZ[r] = 1.f / z;
    }

    const bool write_rwt = (wg == 0);
    #pragma unroll
    for (int k = 0; k < 2; k++) {
        const int idx = t + k * 256;               // float4 index within a row
        #pragma unroll
        for (int r = 0; r < R; r++) {
            float4 vv = ((const float4*)(g_rexp + ((size_t)b*R + r)*N))[idx];
            vv.x *= invZ[r]; vv.y *= invZ[r]; vv.z *= invZ[r]; vv.w *= invZ[r];
            ((float4*)&s_e[r][0])[idx] = vv;
            if (write_rwt) ((float4*)(rwt + ((size_t)b*R + r)*N))[idx] = vv;
        }
    }
    __syncthreads();

    const int wbase = wg * 32 + wi * 4;
    const float4* rp = (const float4*)(Mnew + ((size_t)b * W + wbase) * N);
    const float4* se0 = (const float4*)&s_e[0][0];
    const float4* se1 = (const float4*)&s_e[1][0];
    const float4* se2 = (const float4*)&s_e[2][0];
    const float4* se3 = (const float4*)&s_e[3][0];

    float a[4][R] = {};
    #pragma unroll 4
    for (int k = 0; k < 16; k++) {
        const int idx = lane + k * 32;
        float4 e0 = se0[idx], e1 = se1[idx], e2 = se2[idx], e3 = se3[idx];
        #pragma unroll
        for (int row = 0; row < 4; row++) {
            float4 v = rp[idx + row * (N/4)];
            a[row][0] += v.x*e0.x + v.y*e0.y + v.z*e0.z + v.w*e0.w;
            a[row][1] += v.x*e1.x + v.y*e1.y + v.z*e1.z + v.w*e1.w;
            a[row][2] += v.x*e2.x + v.y*e2.y + v.z*e2.z + v.w*e2.w;
            a[row][3] += v.x*e3.x + v.y*e3.y + v.z*e3.z + v.w*e3.w;
        }
    }
    #pragma unroll
    for (int row = 0; row < 4; row++)
        #pragma unroll
        for (int r = 0; r < R; r++)
            #pragma unroll
            for (int o = 16; o; o >>= 1)
                a[row][r] += __shfl_xor_sync(0xffffffffu, a[row][r], o);
    if (lane == 0) {
        float* optr = mread + (size_t)b * R * W + wbase;
        #pragma unroll
        for (int r = 0; r < R; r++)
            #pragma unroll
            for (int row = 0; row < 4; row++)
                optr[r * W + row] = a[row][r];
    }
}

// ===================== launch =====================
extern "C" void kernel_launch(void* const* d_in, const int* in_sizes, int n_in,
                              void* d_out, int out_size) {
    const float* k_r   = (const float*)d_in[0];
    const float* m_t   = (const float*)d_in[1];
    const float* e_t   = (const float*)d_in[2];
    const float* m_er  = (const float*)d_in[3];
    const float* mem   = (const float*)d_in[4];
    const float* gW    = (const float*)d_in[5];
    const float* gb    = (const float*)d_in[6];
    const float* oW    = (const float*)d_in[7];
    const float* ob    = (const float*)d_in[8];

    float* out   = (float*)d_out;
    float* mread = out;               // (BS,R,W)
    float* Mnew  = out + OFF_MNEW;    // (BS,W,N)
    float* rwt   = out + OFF_RWT;     // (BS,R,N)

    k1_prep <<<dim3(4,  BS), 256>>>(k_r, m_t, e_t, m_er, gW, gb, oW, ob);
    k2_wdist<<<dim3(CH, BS), 256>>>(mem);
    k4_update<<<dim3(CH, BS), 256>>>(mem, Mnew);
    k6_read <<<dim3(W/32, BS), 256>>>(Mnew, rwt, mread);
}

// round 4
// speedup vs baseline: 1.8371x; 1.0487x over previous
#include <cuda_runtime.h>
#include <math.h>

// Fixed shapes for BlurredMem_61950608278069
#define BS 128
#define W  256
#define N  2048
#define R  4
#define EPSF 1e-8f
#define CH 4                       // n-chunks for k2/k4 (512 n per block)

// Output layout: m_read (BS,R,W) | M_new (BS,W,N) | read_wt (BS,R,N)
#define OFF_MNEW (BS*R*W)
#define OFF_RWT  (BS*R*W + BS*W*N)

// -------- scratch (device globals) --------
__device__ float  g_wk[BS*W];         // UNNORMALIZED write key (relu'd)
__device__ float2 g_wmer[BS*W];       // (write_m, erase_vec)
__device__ float4 g_kn4[BS*W];        // normalized read keys (r packed)
__device__ float  g_we[BS*N];         // exp(-cos) unnormalized write weights
__device__ float  g_Zw_part[BS*CH];   // per-block partial sums of g_we
__device__ float  g_rexp[BS*R*N];     // exp(cos) unnormalized read weights
__device__ float  g_Zr_part[BS*CH*R]; // per-block partial sums per read head

// -------- block reduction: warp shuffles + one smem pass (256 threads) ----
template<int NV>
__device__ __forceinline__ void blk_reduce_sum(float (&v)[NV], float* sbuf) {
    const int lane = threadIdx.x & 31, wid = threadIdx.x >> 5;
    #pragma unroll
    for (int i = 0; i < NV; i++) {
        float x = v[i];
        #pragma unroll
        for (int o = 16; o; o >>= 1) x += __shfl_xor_sync(0xffffffffu, x, o);
        if (lane == 0) sbuf[i*8 + wid] = x;
    }
    __syncthreads();
    #pragma unroll
    for (int i = 0; i < NV; i++) {
        float s = 0.f;
        #pragma unroll
        for (int j = 0; j < 8; j++) s += sbuf[i*8 + j];
        v[i] = s;
    }
    __syncthreads();
}

// ===================== K1: per-batch prep (grid 4 x BS) =====================
__global__ void k1_prep(const float* __restrict__ k_r, const float* __restrict__ m_t,
                        const float* __restrict__ e_t, const float* __restrict__ m_er,
                        const float* __restrict__ gW,  const float* __restrict__ gb,
                        const float* __restrict__ oW,  const float* __restrict__ ob) {
    __shared__ float sbuf[48];
    __shared__ __align__(16) float s_cat[2*W];
    const int b = blockIdx.y, t = threadIdx.x;      // t == w in phase 1

    const float wm = tanhf(m_t[b*W + t]);
    const float me = m_er[b*W + t];
    const float ex = expf(e_t[b*W + t]);            // erase softmax, no max pass

    float kv[R];
    #pragma unroll
    for (int r = 0; r < R; r++) kv[r] = tanhf(k_r[(b*R + r)*W + t]);

    float v[6];
    v[0] = ex;
    v[1] = wm * gW[t] + me * gW[W + t];
    #pragma unroll
    for (int r = 0; r < R; r++) v[2+r] = kv[r] * kv[r];
    blk_reduce_sum<6>(v, sbuf);

    const float g = 1.f / (1.f + expf(-(v[1] + gb[0])));
    s_cat[t]     = g * wm;
    s_cat[W + t] = (1.f - g) * me;

    if (blockIdx.x == 0) {
        g_wmer[b*W + t] = make_float2(wm, ex / v[0]);
        #pragma unroll
        for (int r = 0; r < R; r++) kv[r] /= (sqrtf(v[2+r]) + EPSF);
        g_kn4[b*W + t] = make_float4(kv[0], kv[1], kv[2], kv[3]);
    }
    __syncthreads();

    // MLP: 64 rows per block, 4 threads per row (part p handles j = 4i+p)
    const int o = blockIdx.x * 64 + (t >> 2);
    const int p = t & 3;
    const float4* orow4 = (const float4*)(oW + (size_t)o * 2 * W);
    const float4* sc4   = (const float4*)s_cat;
    float acc = 0.f;
    #pragma unroll 8
    for (int i = 0; i < 32; i++) {
        const int j = 4*i + p;
        float4 ow = orow4[j], sc = sc4[j];
        acc += ow.x*sc.x + ow.y*sc.y + ow.z*sc.z + ow.w*sc.w;
    }
    acc += __shfl_xor_sync(0xffffffffu, acc, 1);
    acc += __shfl_xor_sync(0xffffffffu, acc, 2);
    if (p == 0) g_wk[b*W + o] = fmaxf(acc + ob[o], 0.f);
}

// ===================== K2: unnormalized write weights =====================
__global__ void k2_wdist(const float* __restrict__ mem) {
    __shared__ float s_wkn[W];
    __shared__ float sbuf[8];
    const int b = blockIdx.y, t = threadIdx.x;
    const int n0 = blockIdx.x * 512 + 2 * t;

    const float wk = g_wk[b*W + t];
    float v1[1] = { wk * wk };
    blk_reduce_sum<1>(v1, sbuf);
    s_wkn[t] = wk / (sqrtf(v1[0]) + EPSF);
    __syncthreads();

    const float2* mp = (const float2*)(mem + (size_t)b * W * N + n0);
    float2 sq = make_float2(0.f, 0.f), dot = make_float2(0.f, 0.f);
    #pragma unroll 16
    for (int w = 0; w < W; w++) {
        float2 mv = mp[(size_t)w * (N/2)];
        float  kn = s_wkn[w];
        sq.x  += mv.x * mv.x;  sq.y  += mv.y * mv.y;
        dot.x += mv.x * kn;    dot.y += mv.y * kn;
    }
    float2 e;
    e.x = expf(-dot.x / (sqrtf(sq.x) + EPSF));
    e.y = expf(-dot.y / (sqrtf(sq.y) + EPSF));
    *(float2*)&g_we[b*N + n0] = e;

    float z[1] = { e.x + e.y };
    blk_reduce_sum<1>(z, sbuf);
    if (t == 0) g_Zw_part[b*CH + blockIdx.x] = z[0];
}

// ===================== K4: M_new + unnormalized read weights ==============
__global__ void k4_update(const float* __restrict__ mem, float* __restrict__ Mnew) {
    __shared__ float2 s_wmer[W];
    __shared__ float4 s_kn[W];
    __shared__ float  sbuf[32];
    const int b = blockIdx.y, t = threadIdx.x;
    const int n0 = blockIdx.x * 512 + 2 * t;
    s_wmer[t] = g_wmer[b*W + t];
    s_kn[t]   = g_kn4[b*W + t];

    float zw = 0.f;
    #pragma unroll
    for (int c = 0; c < CH; c++) zw += g_Zw_part[b*CH + c];
    __syncthreads();

    float2 wev = *(const float2*)&g_we[b*N + n0];
    const float2 wwt = make_float2(wev.x / zw, wev.y / zw);
    const float2* mp = (const float2*)(mem  + (size_t)b * W * N + n0);
    float2*       op = (float2*)(Mnew + (size_t)b * W * N + n0);

    float2 sq = make_float2(0.f, 0.f);
    float2 d0 = sq, d1 = sq, d2 = sq, d3 = sq;
    #pragma unroll 16
    for (int w = 0; w < W; w++) {
        float2 mv = mp[(size_t)w * (N/2)];
        float2 we = s_wmer[w];
        float2 mn;
        mn.x = mv.x * (1.f - we.y * wwt.x) + we.x * wwt.x;
        mn.y = mv.y * (1.f - we.y * wwt.y) + we.x * wwt.y;
        op[(size_t)w * (N/2)] = mn;
        sq.x += mn.x * mn.x;  sq.y += mn.y * mn.y;
        float4 k = s_kn[w];
        d0.x += mn.x * k.x;  d0.y += mn.y * k.x;
        d1.x += mn.x * k.y;  d1.y += mn.y * k.y;
        d2.x += mn.x * k.z;  d2.y += mn.y * k.z;
        d3.x += mn.x * k.w;  d3.y += mn.y * k.w;
    }
    const float ivx = 1.f / (sqrtf(sq.x) + EPSF);
    const float ivy = 1.f / (sqrtf(sq.y) + EPSF);
    float2 e0 = make_float2(expf(d0.x*ivx), expf(d0.y*ivy));
    float2 e1 = make_float2(expf(d1.x*ivx), expf(d1.y*ivy));
    float2 e2 = make_float2(expf(d2.x*ivx), expf(d2.y*ivy));
    float2 e3 = make_float2(expf(d3.x*ivx), expf(d3.y*ivy));
    *(float2*)&g_rexp[((size_t)b*R + 0)*N + n0] = e0;
    *(float2*)&g_rexp[((size_t)b*R + 1)*N + n0] = e1;
    *(float2*)&g_rexp[((size_t)b*R + 2)*N + n0] = e2;
    *(float2*)&g_rexp[((size_t)b*R + 3)*N + n0] = e3;

    float zr[R] = { e0.x+e0.y, e1.x+e1.y, e2.x+e2.y, e3.x+e3.y };
    blk_reduce_sum<R>(zr, sbuf);
    if (t == 0) {
        #pragma unroll
        for (int r = 0; r < R; r++) g_Zr_part[(b*CH + blockIdx.x)*R + r] = zr[r];
    }
}

// ===================== K6: rwt output + m_read ============================
// block = (group of 32 rows, b); each warp owns 4 consecutive M_new rows.
// Software prefetch: next iteration's 4 row-loads issued before current FMAs
// so ~8 LDG.128 are outstanding per warp (latency hiding at 3 blocks/SM).
__global__ void __launch_bounds__(256, 3)
k6_read(const float* __restrict__ Mnew, float* __restrict__ rwt,
        float* __restrict__ mread) {
    __shared__ __align__(16) float s_e[R][N];     // 32 KB
    const int b = blockIdx.y, wg = blockIdx.x;
    const int t = threadIdx.x, lane = t & 31, wi = t >> 5;

    float invZ[R];
    #pragma unroll
    for (int r = 0; r < R; r++) {
        float z = 0.f;
        #pragma unroll
        for (int c = 0; c < CH; c++) z += g_Zr_part[(b*CH + c)*R + r];
        invZ[r] = 1.f / z;
    }

    const bool write_rwt = (wg == 0);
    #pragma unroll
    for (int k = 0; k < 2; k++) {
        const int idx = t + k * 256;               // float4 index within a row
        #pragma unroll
        for (int r = 0; r < R; r++) {
            float4 vv = ((const float4*)(g_rexp + ((size_t)b*R + r)*N))[idx];
            vv.x *= invZ[r]; vv.y *= invZ[r]; vv.z *= invZ[r]; vv.w *= invZ[r];
            ((float4*)&s_e[r][0])[idx] = vv;
            if (write_rwt) ((float4*)(rwt + ((size_t)b*R + r)*N))[idx] = vv;
        }
    }
    __syncthreads();

    const int wbase = wg * 32 + wi * 4;
    const float4* rp  = (const float4*)(Mnew + ((size_t)b * W + wbase) * N);
    const float4* se0 = (const float4*)&s_e[0][0];
    const float4* se1 = (const float4*)&s_e[1][0];
    const float4* se2 = (const float4*)&s_e[2][0];
    const float4* se3 = (const float4*)&s_e[3][0];

    float a[4][R] = {};
    float4 v[4];
    #pragma unroll
    for (int row = 0; row < 4; row++) v[row] = rp[lane + row * (N/4)];

    #pragma unroll 4
    for (int k = 0; k < 16; k++) {
        const int idx  = lane + k * 32;
        const int pidx = (k < 15) ? idx + 32 : idx;   // prefetch index (clamped)
        float4 nv[4];
        #pragma unroll
        for (int row = 0; row < 4; row++) nv[row] = rp[pidx + row * (N/4)];

        float4 e0 = se0[idx], e1 = se1[idx], e2 = se2[idx], e3 = se3[idx];
        #pragma unroll
        for (int row = 0; row < 4; row++) {
            float4 mv = v[row];
            a[row][0] += mv.x*e0.x + mv.y*e0.y + mv.z*e0.z + mv.w*e0.w;
            a[row][1] += mv.x*e1.x + mv.y*e1.y + mv.z*e1.z + mv.w*e1.w;
            a[row][2] += mv.x*e2.x + mv.y*e2.y + mv.z*e2.z + mv.w*e2.w;
            a[row][3] += mv.x*e3.x + mv.y*e3.y + mv.z*e3.z + mv.w*e3.w;
        }
        #pragma unroll
        for (int row = 0; row < 4; row++) v[row] = nv[row];
    }

    #pragma unroll
    for (int row = 0; row < 4; row++)
        #pragma unroll
        for (int r = 0; r < R; r++)
            #pragma unroll
            for (int o = 16; o; o >>= 1)
                a[row][r] += __shfl_xor_sync(0xffffffffu, a[row][r], o);
    if (lane == 0) {
        float* optr = mread + (size_t)b * R * W + wbase;
        #pragma unroll
        for (int r = 0; r < R; r++)
            #pragma unroll
            for (int row = 0; row < 4; row++)
                optr[r * W + row] = a[row][r];
    }
}

// ===================== launch =====================
extern "C" void kernel_launch(void* const* d_in, const int* in_sizes, int n_in,
                              void* d_out, int out_size) {
    const float* k_r   = (const float*)d_in[0];
    const float* m_t   = (const float*)d_in[1];
    const float* e_t   = (const float*)d_in[2];
    const float* m_er  = (const float*)d_in[3];
    const float* mem   = (const float*)d_in[4];
    const float* gW    = (const float*)d_in[5];
    const float* gb    = (const float*)d_in[6];
    const float* oW    = (const float*)d_in[7];
    const float* ob    = (const float*)d_in[8];

    float* out   = (float*)d_out;
    float* mread = out;               // (BS,R,W)
    float* Mnew  = out + OFF_MNEW;    // (BS,W,N)
    float* rwt   = out + OFF_RWT;     // (BS,R,N)

    k1_prep <<<dim3(4,  BS), 256>>>(k_r, m_t, e_t, m_er, gW, gb, oW, ob);
    k2_wdist<<<dim3(CH, BS), 256>>>(mem);
    k4_update<<<dim3(CH, BS), 256>>>(mem, Mnew);
    k6_read <<<dim3(W/32, BS), 256>>>(Mnew, rwt, mread);
}